// round 1
// baseline (speedup 1.0000x reference)
#include <cuda_runtime.h>
#include <math.h>

#define NNODES 100000
#define FIN    512
#define HID    256
#define NC     40
#define KSTEPS 10
#define EMAX   3200000
#define ALPHA  0.1f

// ---------------- device scratch (no allocations allowed) ----------------
__device__ float g_hid[NNODES * HID];      // ~102 MB
__device__ float g_h  [NNODES * NC];       // 16 MB
__device__ float g_zA [NNODES * NC];
__device__ float g_zB [NNODES * NC];
__device__ float g_dinv[NNODES];
__device__ int   g_deg [NNODES];
__device__ int   g_rowptr[NNODES + 1];
__device__ int   g_fill[NNODES];
__device__ int   g_colidx[EMAX];
__device__ float g_ew   [EMAX];

// ---------------- graph preprocessing ----------------
__global__ void zero_deg_kernel() {
    int i = blockIdx.x * blockDim.x + threadIdx.x;
    if (i < NNODES) g_deg[i] = 0;
}

__global__ void count_deg_kernel(const int* __restrict__ ei, int E) {
    int e = blockIdx.x * blockDim.x + threadIdx.x;
    if (e < E) atomicAdd(&g_deg[ei[e]], 1);
}

// single-block exclusive scan over g_deg -> g_rowptr, also dinv + fill init
__global__ void scan_kernel(int E) {
    const int T = 1024;
    const int CH = (NNODES + T - 1) / T;
    int t = threadIdx.x;
    int beg = t * CH;
    int end = beg + CH; if (end > NNODES) end = NNODES;
    if (beg > NNODES) beg = NNODES;

    int sum = 0;
    for (int i = beg; i < end; i++) sum += g_deg[i];

    __shared__ int sh[1024];
    sh[t] = sum;
    __syncthreads();
    // Hillis-Steele inclusive scan
    for (int off = 1; off < T; off <<= 1) {
        int v = (t >= off) ? sh[t - off] : 0;
        __syncthreads();
        sh[t] += v;
        __syncthreads();
    }
    int offset = sh[t] - sum;   // exclusive prefix for this chunk

    int running = offset;
    for (int i = beg; i < end; i++) {
        g_rowptr[i] = running;
        g_fill[i]   = running;
        g_dinv[i]   = rsqrtf((float)(g_deg[i] + 1));   // +1 self-loop
        running += g_deg[i];
    }
    if (t == T - 1) g_rowptr[NNODES] = sh[T - 1];  // == E
}

__global__ void scatter_kernel(const int* __restrict__ ei, int E) {
    int e = blockIdx.x * blockDim.x + threadIdx.x;
    if (e >= E) return;
    int r = ei[e];          // destination
    int c = ei[E + e];      // source
    int pos = atomicAdd(&g_fill[r], 1);
    g_colidx[pos] = c;
    g_ew[pos] = g_dinv[r] * g_dinv[c];
}

// ---------------- GEMM1: h1 = relu(x @ W1 + b1)  [100000,512]x[512,256] ----------------
// BM=128 BN=64 BK=16, 256 threads, thread tile 8x4
__global__ __launch_bounds__(256) void gemm1_kernel(
    const float* __restrict__ X, const float* __restrict__ W1, const float* __restrict__ b1)
{
    __shared__ float As[16][128];
    __shared__ float Bs[16][64];

    int tid = threadIdx.x;
    int m0 = blockIdx.x * 128;
    int n0 = blockIdx.y * 64;

    int tx = tid & 15;       // 16 cols of threads -> 4 outputs each
    int ty = tid >> 4;       // 16 rows of threads -> 8 outputs each

    float acc[8][4];
    #pragma unroll
    for (int i = 0; i < 8; i++)
        #pragma unroll
        for (int j = 0; j < 4; j++) acc[i][j] = 0.0f;

    for (int k0 = 0; k0 < FIN; k0 += 16) {
        // load A tile: 128 rows x 16 k = 512 float4, 2 per thread
        #pragma unroll
        for (int l = 0; l < 2; l++) {
            int f = tid + l * 256;        // 0..511
            int m = f >> 2;               // 0..127
            int kq = f & 3;               // 0..3 -> k = kq*4
            float4 v = make_float4(0.f, 0.f, 0.f, 0.f);
            if (m0 + m < NNODES)
                v = *(const float4*)&X[(size_t)(m0 + m) * FIN + k0 + kq * 4];
            As[kq * 4 + 0][m] = v.x;
            As[kq * 4 + 1][m] = v.y;
            As[kq * 4 + 2][m] = v.z;
            As[kq * 4 + 3][m] = v.w;
        }
        // load B tile: 16 k x 64 n = 256 float4, 1 per thread
        {
            int kr = tid >> 4;            // 0..15
            int nq = tid & 15;            // 0..15 -> n = nq*4
            float4 v = *(const float4*)&W1[(size_t)(k0 + kr) * HID + n0 + nq * 4];
            *(float4*)&Bs[kr][nq * 4] = v;
        }
        __syncthreads();

        #pragma unroll
        for (int k = 0; k < 16; k++) {
            float4 a0 = *(float4*)&As[k][ty * 8];
            float4 a1 = *(float4*)&As[k][ty * 8 + 4];
            float4 b  = *(float4*)&Bs[k][tx * 4];
            float av[8] = {a0.x, a0.y, a0.z, a0.w, a1.x, a1.y, a1.z, a1.w};
            float bv[4] = {b.x, b.y, b.z, b.w};
            #pragma unroll
            for (int i = 0; i < 8; i++)
                #pragma unroll
                for (int j = 0; j < 4; j++)
                    acc[i][j] += av[i] * bv[j];
        }
        __syncthreads();
    }

    float bias[4];
    #pragma unroll
    for (int j = 0; j < 4; j++) bias[j] = b1[n0 + tx * 4 + j];

    #pragma unroll
    for (int i = 0; i < 8; i++) {
        int m = m0 + ty * 8 + i;
        if (m < NNODES) {
            float4 v;
            v.x = fmaxf(acc[i][0] + bias[0], 0.0f);
            v.y = fmaxf(acc[i][1] + bias[1], 0.0f);
            v.z = fmaxf(acc[i][2] + bias[2], 0.0f);
            v.w = fmaxf(acc[i][3] + bias[3], 0.0f);
            *(float4*)&g_hid[(size_t)m * HID + n0 + tx * 4] = v;
        }
    }
}

// ---------------- GEMM2: h = hid @ W2 + b2  [100000,256]x[256,40] ----------------
// BM=64 BN=40 BK=32, 256 threads, thread tile 2x5
__global__ __launch_bounds__(256) void gemm2_kernel(
    const float* __restrict__ W2, const float* __restrict__ b2)
{
    __shared__ float Hs[32][65];
    __shared__ float Ws[32][40];

    int tid = threadIdx.x;
    int m0 = blockIdx.x * 64;
    int tx = tid & 7;        // 8 -> 5 cols each
    int ty = tid >> 3;       // 32 -> 2 rows each

    float acc[2][5];
    #pragma unroll
    for (int r = 0; r < 2; r++)
        #pragma unroll
        for (int j = 0; j < 5; j++) acc[r][j] = 0.0f;

    for (int k0 = 0; k0 < HID; k0 += 32) {
        // load Hs: 64 rows x 32 k, coalesced over k
        {
            int kk = tid & 31;
            int mb = tid >> 5;   // 0..7
            #pragma unroll
            for (int mi = 0; mi < 8; mi++) {
                int m = mi * 8 + mb;
                float v = 0.0f;
                if (m0 + m < NNODES)
                    v = g_hid[(size_t)(m0 + m) * HID + k0 + kk];
                Hs[kk][m] = v;
            }
        }
        // load Ws: 32 x 40 = 1280, 5 per thread
        #pragma unroll
        for (int l = 0; l < 5; l++) {
            int idx = tid + l * 256;
            int kr = idx / 40;
            int n = idx - kr * 40;
            Ws[kr][n] = W2[(size_t)(k0 + kr) * NC + n];
        }
        __syncthreads();

        #pragma unroll
        for (int k = 0; k < 32; k++) {
            float a0 = Hs[k][ty * 2];
            float a1 = Hs[k][ty * 2 + 1];
            #pragma unroll
            for (int j = 0; j < 5; j++) {
                float b = Ws[k][tx * 5 + j];
                acc[0][j] += a0 * b;
                acc[1][j] += a1 * b;
            }
        }
        __syncthreads();
    }

    #pragma unroll
    for (int r = 0; r < 2; r++) {
        int m = m0 + ty * 2 + r;
        if (m < NNODES) {
            #pragma unroll
            for (int j = 0; j < 5; j++) {
                int n = tx * 5 + j;
                g_h[(size_t)m * NC + n] = acc[r][j] + b2[n];
            }
        }
    }
}

// ---------------- APPNP propagation step: zout = 0.9*A_norm*zin + 0.1*h ----------------
// warp per row, lane c handles channels c and (c+32 if c<8)
__global__ __launch_bounds__(256) void spmm_kernel(int srcSel, int dstSel) {
    const float* zin  = (srcSel == 0) ? g_h : (srcSel == 1 ? g_zA : g_zB);
    float*       zout = (dstSel == 1) ? g_zA : g_zB;

    int w = (blockIdx.x * blockDim.x + threadIdx.x) >> 5;
    int lane = threadIdx.x & 31;
    if (w >= NNODES) return;
    int r = w;
    int s = g_rowptr[r];
    int e = g_rowptr[r + 1];

    float acc0 = 0.0f, acc1 = 0.0f;
    for (int j = s; j < e; j++) {
        float wt = g_ew[j];
        int ci = g_colidx[j];
        const float* zb = zin + (size_t)ci * NC;
        acc0 += wt * zb[lane];
        if (lane < 8) acc1 += wt * zb[32 + lane];
    }
    // self loop
    float dv = g_dinv[r];
    float ws = dv * dv;
    const float* zr = zin + (size_t)r * NC;
    acc0 += ws * zr[lane];
    if (lane < 8) acc1 += ws * zr[32 + lane];

    const float* hr = g_h + (size_t)r * NC;
    float* zo = zout + (size_t)r * NC;
    zo[lane] = (1.0f - ALPHA) * acc0 + ALPHA * hr[lane];
    if (lane < 8) zo[32 + lane] = (1.0f - ALPHA) * acc1 + ALPHA * hr[32 + lane];
}

// ---------------- log_softmax over 40 classes, warp per row ----------------
__global__ __launch_bounds__(256) void logsoftmax_kernel(float* __restrict__ out) {
    int w = (blockIdx.x * blockDim.x + threadIdx.x) >> 5;
    int lane = threadIdx.x & 31;
    if (w >= NNODES) return;

    const float* zr = g_zB + (size_t)w * NC;
    float v0 = zr[lane];
    float v1 = (lane < 8) ? zr[32 + lane] : -3.4e38f;

    float m = fmaxf(v0, v1);
    #pragma unroll
    for (int off = 16; off > 0; off >>= 1)
        m = fmaxf(m, __shfl_xor_sync(0xffffffff, m, off));

    float s = __expf(v0 - m) + ((lane < 8) ? __expf(v1 - m) : 0.0f);
    #pragma unroll
    for (int off = 16; off > 0; off >>= 1)
        s += __shfl_xor_sync(0xffffffff, s, off);

    float lse = m + logf(s);
    float* o = out + (size_t)w * NC;
    o[lane] = v0 - lse;
    if (lane < 8) o[32 + lane] = v1 - lse;
}

// ---------------- launch ----------------
extern "C" void kernel_launch(void* const* d_in, const int* in_sizes, int n_in,
                              void* d_out, int out_size) {
    const float* x  = (const float*)d_in[0];
    const float* W1 = (const float*)d_in[1];
    const float* b1 = (const float*)d_in[2];
    const float* W2 = (const float*)d_in[3];
    const float* b2 = (const float*)d_in[4];
    const int*   ei = (const int*)d_in[5];
    float* out = (float*)d_out;
    int E = in_sizes[5] / 2;

    // graph preprocessing -> CSR + normalized weights
    zero_deg_kernel<<<(NNODES + 255) / 256, 256>>>();
    count_deg_kernel<<<(E + 255) / 256, 256>>>(ei, E);
    scan_kernel<<<1, 1024>>>(E);
    scatter_kernel<<<(E + 255) / 256, 256>>>(ei, E);

    // MLP encoder
    dim3 g1((NNODES + 127) / 128, HID / 64);
    gemm1_kernel<<<g1, 256>>>(x, W1, b1);
    gemm2_kernel<<<(NNODES + 63) / 64, 256>>>(W2, b2);

    // K=10 APPNP steps; src: 0=h 1=zA 2=zB, dst: 1=zA 2=zB
    int spmmGrid = (NNODES * 32 + 255) / 256;
    for (int i = 1; i <= KSTEPS; i++) {
        int src = (i == 1) ? 0 : ((i & 1) ? 2 : 1);
        int dst = (i & 1) ? 1 : 2;
        spmm_kernel<<<spmmGrid, 256>>>(src, dst);
    }

    // final z is in g_zB (K even)
    logsoftmax_kernel<<<spmmGrid, 256>>>(out);
}